// round 13
// baseline (speedup 1.0000x reference)
#include <cuda_runtime.h>
#include <cuda_bf16.h>
#include <mma.h>
#include <cstdint>
#include <cstddef>

using namespace nvcuda;

// Problem constants
#define Bc   256
#define HIDc 512
#define Hc   8
#define Dc   64
#define FFc  2048
#define Lc   6

#define EPS_ATTN 1e-6f
#define EPS_LN   1e-5f

#define MNc (Bc * HIDc)        // 131072
#define WPL 3145728            // weight elems per layer (Wq,Wk,Wv,Wo,W1,W2)
#define WTOT (Lc * WPL)        // 18874368
// per-layer weight offsets inside the packed hi/lo arrays
#define OFF_WQ 0
#define OFF_WK 262144
#define OFF_WV 524288
#define OFF_WO 786432
#define OFF_W1 1048576
#define OFF_W2 2097152

// ---------------- scratch (device globals; no allocations allowed) ----------
__device__ float          g_h[MNc];                 // fp32 h (residual path)
__device__ __nv_bfloat16  g_hh[MNc],  g_hl[MNc];    // h hi/lo
__device__ __nv_bfloat16  g_ah[MNc],  g_al[MNc];    // attn hi/lo
__device__ __nv_bfloat16  g_fh[Bc * FFc], g_fl[Bc * FFc];  // ff hi/lo
__device__ float          g_part[8 * MNc];          // split-K partials (O / FF2)
__device__ float          g_qkvp[6 * MNc];          // QKV partials: slab = mat*2+split
__device__ __nv_bfloat16  g_whi[WTOT], g_wlo[WTOT]; // packed bf16 hi/lo weights

// ---------------- weight hi/lo split (runs once per call) -------------------
// 8 elems per thread; 16B stores for hi and lo.
__global__ __launch_bounds__(256) void split_weights_kernel(
    const float* __restrict__ Wq, const float* __restrict__ Wk,
    const float* __restrict__ Wv, const float* __restrict__ Wo,
    const float* __restrict__ W1, const float* __restrict__ W2,
    __nv_bfloat16* __restrict__ hi, __nv_bfloat16* __restrict__ lo)
{
    size_t i = ((size_t)blockIdx.x * 256 + threadIdx.x) * 8;
    if (i >= WTOT) return;
    int l = (int)(i / WPL);
    size_t r = i - (size_t)l * WPL;
    const float* src;
    if      (r < 262144)  src = Wq + (size_t)l * 262144  + r;
    else if (r < 524288)  src = Wk + (size_t)l * 262144  + (r - 262144);
    else if (r < 786432)  src = Wv + (size_t)l * 262144  + (r - 524288);
    else if (r < 1048576) src = Wo + (size_t)l * 262144  + (r - 786432);
    else if (r < 2097152) src = W1 + (size_t)l * 1048576 + (r - 1048576);
    else                  src = W2 + (size_t)l * 1048576 + (r - 2097152);
    float4 v0 = *(const float4*)src;
    float4 v1 = *(const float4*)(src + 4);
    float xs[8] = {v0.x, v0.y, v0.z, v0.w, v1.x, v1.y, v1.z, v1.w};
    __align__(16) __nv_bfloat16 th[8], tl[8];
#pragma unroll
    for (int e = 0; e < 8; e++) {
        __nv_bfloat16 h = __float2bfloat16(xs[e]);
        th[e] = h;
        tl[e] = __float2bfloat16(xs[e] - __bfloat162float(h));
    }
    *(float4*)&hi[i] = *(float4*)th;
    *(float4*)&lo[i] = *(float4*)tl;
}

// ---------------- embedding + positional encoding ---------------------------
__global__ __launch_bounds__(256) void embed_kernel(
    const int* __restrict__ x, const int* __restrict__ pos_p,
    const float* __restrict__ emb, float* __restrict__ h,
    __nv_bfloat16* __restrict__ hh, __nv_bfloat16* __restrict__ hl)
{
    int i = blockIdx.x * 256 + threadIdx.x;           // 0 .. B*HID-1
    int b = i >> 9;
    int c = i & 511;
    float posf = (float)(*pos_p);
    int j2 = c & ~1;                                   // 2*j
    float e = (float)j2 * (1.0f / (float)HIDc);
    float ang = posf * powf(10000.0f, -e);
    float pe = (c & 1) ? cosf(ang) : sinf(ang);
    float v = emb[(size_t)x[b] * HIDc + c] + pe;
    h[i] = v;
    __nv_bfloat16 vh = __float2bfloat16(v);
    hh[i] = vh;
    hl[i] = __float2bfloat16(v - __bfloat162float(vh));
}

// ---------------- bf16 hi/lo tensor-core GEMM --------------------------------
// C[M,N] = A[M,K] @ W[K,N] over k in [k0, k0+kLen), fp32-class accuracy via
// 3 bf16 MMAs: ahi*bhi + alo*bhi + ahi*blo.  64x64 tile, BK=32, 128 threads
// (4 warps, each 32x32 of C), smem ping-pong + register prefetch.
// Epilogue: if oh != nullptr, write bf16 hi/lo (bias/act applied); else fp32 C.
#define BKb  32
#define LDAb 40
#define LDBb 72

__device__ __forceinline__ void gemm_bf16_body(
    const __nv_bfloat16* __restrict__ Ah, const __nv_bfloat16* __restrict__ Al,
    const __nv_bfloat16* __restrict__ Wh, const __nv_bfloat16* __restrict__ Wl,
    const float* __restrict__ bias, float* __restrict__ C,
    __nv_bfloat16* __restrict__ oh, __nv_bfloat16* __restrict__ ol,
    int N, int K, int k0, int kLen, int act)
{
    __shared__ __align__(16) __nv_bfloat16 sA[2][2][64][LDAb];  // [buf][hi/lo]
    __shared__ __align__(16) __nv_bfloat16 sB[2][2][BKb][LDBb];

    const int tid   = threadIdx.x;           // 128 threads
    const int warp  = tid >> 5;
    const int wm    = warp & 1;              // 2 m-slices of 32
    const int wn    = warp >> 1;             // 2 n-slices of 32
    const int row0  = blockIdx.y * 64;
    const int col0  = blockIdx.x * 64;

    const __nv_bfloat16* Agh = Ah + (size_t)row0 * K + k0;
    const __nv_bfloat16* Agl = Al + (size_t)row0 * K + k0;
    const __nv_bfloat16* Wgh = Wh + (size_t)k0 * N + col0;
    const __nv_bfloat16* Wgl = Wl + (size_t)k0 * N + col0;

    // global slots: A tile 64x32 bf16 = 256 float4; B tile 32x64 = 256 float4
    int ar[2], ac8[2], br[2], bc8[2];
#pragma unroll
    for (int u = 0; u < 2; u++) {
        int s = tid + u * 128;
        ar[u] = s >> 2;  ac8[u] = (s & 3) * 8;
        br[u] = s >> 3;  bc8[u] = (s & 7) * 8;
    }

    float4 pAh[2], pAl[2], pBh[2], pBl[2];
#pragma unroll
    for (int u = 0; u < 2; u++) {
        pAh[u] = *(const float4*)(Agh + (size_t)ar[u] * K + ac8[u]);
        pAl[u] = *(const float4*)(Agl + (size_t)ar[u] * K + ac8[u]);
        pBh[u] = *(const float4*)(Wgh + (size_t)br[u] * N + bc8[u]);
        pBl[u] = *(const float4*)(Wgl + (size_t)br[u] * N + bc8[u]);
    }
#pragma unroll
    for (int u = 0; u < 2; u++) {
        *(float4*)&sA[0][0][ar[u]][ac8[u]] = pAh[u];
        *(float4*)&sA[0][1][ar[u]][ac8[u]] = pAl[u];
        *(float4*)&sB[0][0][br[u]][bc8[u]] = pBh[u];
        *(float4*)&sB[0][1][br[u]][bc8[u]] = pBl[u];
    }
    __syncthreads();

    wmma::fragment<wmma::accumulator, 16, 16, 16, float> acc[2][2];
#pragma unroll
    for (int mi = 0; mi < 2; mi++)
#pragma unroll
        for (int ni = 0; ni < 2; ni++) wmma::fill_fragment(acc[mi][ni], 0.0f);

    const int ntiles = kLen / BKb;
    for (int t = 0; t < ntiles; t++) {
        const int cur = t & 1, nxt = cur ^ 1;

        if (t + 1 < ntiles) {                // prefetch next tile into regs
            const __nv_bfloat16* Agh2 = Agh + (t + 1) * BKb;
            const __nv_bfloat16* Agl2 = Agl + (t + 1) * BKb;
            const __nv_bfloat16* Wgh2 = Wgh + (size_t)(t + 1) * BKb * N;
            const __nv_bfloat16* Wgl2 = Wgl + (size_t)(t + 1) * BKb * N;
#pragma unroll
            for (int u = 0; u < 2; u++) {
                pAh[u] = *(const float4*)(Agh2 + (size_t)ar[u] * K + ac8[u]);
                pAl[u] = *(const float4*)(Agl2 + (size_t)ar[u] * K + ac8[u]);
                pBh[u] = *(const float4*)(Wgh2 + (size_t)br[u] * N + bc8[u]);
                pBl[u] = *(const float4*)(Wgl2 + (size_t)br[u] * N + bc8[u]);
            }
        }

#pragma unroll
        for (int ks = 0; ks < 2; ks++) {
            wmma::fragment<wmma::matrix_a, 16, 16, 16, __nv_bfloat16, wmma::row_major> a_hi[2], a_lo[2];
            wmma::fragment<wmma::matrix_b, 16, 16, 16, __nv_bfloat16, wmma::row_major> b_hi[2], b_lo[2];
#pragma unroll
            for (int mi = 0; mi < 2; mi++) {
                int mrow = wm * 32 + mi * 16;
                wmma::load_matrix_sync(a_hi[mi], &sA[cur][0][mrow][ks * 16], LDAb);
                wmma::load_matrix_sync(a_lo[mi], &sA[cur][1][mrow][ks * 16], LDAb);
            }
#pragma unroll
            for (int ni = 0; ni < 2; ni++) {
                int ncol = wn * 32 + ni * 16;
                wmma::load_matrix_sync(b_hi[ni], &sB[cur][0][ks * 16][ncol], LDBb);
                wmma::load_matrix_sync(b_lo[ni], &sB[cur][1][ks * 16][ncol], LDBb);
            }
#pragma unroll
            for (int mi = 0; mi < 2; mi++)
#pragma unroll
                for (int ni = 0; ni < 2; ni++) {
                    wmma::mma_sync(acc[mi][ni], a_hi[mi], b_hi[ni], acc[mi][ni]);
                    wmma::mma_sync(acc[mi][ni], a_lo[mi], b_hi[ni], acc[mi][ni]);
                    wmma::mma_sync(acc[mi][ni], a_hi[mi], b_lo[ni], acc[mi][ni]);
                }
        }

        if (t + 1 < ntiles) {                // commit prefetched tile
#pragma unroll
            for (int u = 0; u < 2; u++) {
                *(float4*)&sA[nxt][0][ar[u]][ac8[u]] = pAh[u];
                *(float4*)&sA[nxt][1][ar[u]][ac8[u]] = pAl[u];
                *(float4*)&sB[nxt][0][br[u]][bc8[u]] = pBh[u];
                *(float4*)&sB[nxt][1][br[u]][bc8[u]] = pBl[u];
            }
        }
        __syncthreads();
    }

    // epilogue: fragments -> smem C tile (aliases sA) -> bias/act -> gmem
    float* cT = (float*)&sA[0][0][0][0];     // 64x64 fp32 = 16KB
#pragma unroll
    for (int mi = 0; mi < 2; mi++)
#pragma unroll
        for (int ni = 0; ni < 2; ni++)
            wmma::store_matrix_sync(&cT[(wm * 32 + mi * 16) * 64 + wn * 32 + ni * 16],
                                    acc[mi][ni], 64, wmma::mem_row_major);
    __syncthreads();

#pragma unroll
    for (int u = 0; u < 8; u++) {
        int s = tid + u * 128;               // 1024 float4 slots
        int r = s >> 4, c4 = (s & 15) * 4;
        float4 vv = *(const float4*)&cT[r * 64 + c4];
        float* pv = (float*)&vv;
        if (bias) {
#pragma unroll
            for (int e = 0; e < 4; e++) pv[e] += bias[col0 + c4 + e];
        }
        if (act == 2) {
#pragma unroll
            for (int e = 0; e < 4; e++) pv[e] = fmaxf(pv[e], 0.0f);
        }
        size_t o = (size_t)(row0 + r) * N + col0 + c4;
        if (oh) {                            // bf16 hi/lo output
            __align__(8) __nv_bfloat16 th[4], tl[4];
#pragma unroll
            for (int e = 0; e < 4; e++) {
                __nv_bfloat16 vh = __float2bfloat16(pv[e]);
                th[e] = vh;
                tl[e] = __float2bfloat16(pv[e] - __bfloat162float(vh));
            }
            *(uint2*)&oh[o] = *(uint2*)th;
            *(uint2*)&ol[o] = *(uint2*)tl;
        } else {
            *(float4*)&C[o] = vv;
        }
    }
}

// Generic GEMM; grid.z = split-K count; split z writes partial slab z of C.
__global__ __launch_bounds__(128) void gemm_bf16_kernel(
    const __nv_bfloat16* __restrict__ Ah, const __nv_bfloat16* __restrict__ Al,
    const __nv_bfloat16* __restrict__ Wh, const __nv_bfloat16* __restrict__ Wl,
    const float* __restrict__ bias, float* __restrict__ C,
    __nv_bfloat16* __restrict__ oh, __nv_bfloat16* __restrict__ ol,
    int M, int N, int K, int act)
{
    int kLen = K / gridDim.z;
    int k0   = blockIdx.z * kLen;
    if (C) C += (size_t)blockIdx.z * M * N;
    gemm_bf16_body(Ah, Al, Wh, Wl, bias, C, oh, ol, N, K, k0, kLen, act);
}

// QKV GEMM, split-K=2 per matrix: grid.z in 0..5, mat = z>>1, split = z&1.
__global__ __launch_bounds__(128) void gemm_qkv_bf16_kernel(
    const __nv_bfloat16* __restrict__ Ah, const __nv_bfloat16* __restrict__ Al,
    const __nv_bfloat16* __restrict__ WLh, const __nv_bfloat16* __restrict__ WLl,
    float* __restrict__ qkvp)
{
    int mat   = blockIdx.z >> 1;
    int split = blockIdx.z & 1;
    const __nv_bfloat16* Wh = WLh + (size_t)mat * 262144;
    const __nv_bfloat16* Wl = WLl + (size_t)mat * 262144;
    float* C = qkvp + (size_t)blockIdx.z * MNc;
    gemm_bf16_body(Ah, Al, Wh, Wl, nullptr, C, nullptr, nullptr, HIDc, HIDc,
                   split * (HIDc / 2), HIDc / 2, 0);
}

// ---------------- fused linear-attention state update (vectorized) -----------
// One block per (b,h). Fuses: QKV split-K(2) reduce + bias + elu(+1);
// S_out = S + k v^T, num = q . S_out, den = q.(Z+k)+eps, attn = num/den (hi/lo).
// float4 on the S stream: thread handles 4 cols x 4 rows.
#define RSTR 68   // padded stride of partial-num matrix (float4-aligned, cf-free)

__global__ __launch_bounds__(256) void attn_state_kernel(
    const float* __restrict__ S_in, const float* __restrict__ Z_in,
    const float* __restrict__ qkvp,
    const float* __restrict__ bq, const float* __restrict__ bk,
    const float* __restrict__ bv,
    float* __restrict__ S_out, float* __restrict__ Z_out,
    __nv_bfloat16* __restrict__ ah, __nv_bfloat16* __restrict__ al)
{
    int bh = blockIdx.x;                 // 0 .. B*H-1
    int t  = threadIdx.x;                // 256 threads
    __shared__ float qs[Dc], ks[Dc], vs[Dc];
    __shared__ float rnum[16 * RSTR];
    __shared__ float red64[Dc];
    __shared__ float s_den;

    int voff = bh * Dc;                  // == b*HID + h*D
    if (t < Dc) {
        int c = ((bh & (Hc - 1)) << 6) + t;          // column within HID
        float qq = bq[c] + qkvp[voff + t]                   + qkvp[MNc + voff + t];
        float kk = bk[c] + qkvp[2 * (size_t)MNc + voff + t] + qkvp[3 * (size_t)MNc + voff + t];
        float vv = bv[c] + qkvp[4 * (size_t)MNc + voff + t] + qkvp[5 * (size_t)MNc + voff + t];
        qq = (qq > 0.0f) ? (qq + 1.0f) : expf(qq);   // elu(x)+1
        kk = (kk > 0.0f) ? (kk + 1.0f) : expf(kk);
        qs[t] = qq; ks[t] = kk; vs[t] = vv;
        float zn = Z_in[voff + t] + kk;
        Z_out[voff + t] = zn;
        red64[t] = qq * zn;
    }
    __syncthreads();
    if (t < 32) {
        float s = red64[t] + red64[t + 32];
#pragma unroll
        for (int o = 16; o > 0; o >>= 1) s += __shfl_down_sync(0xffffffffu, s, o);
        if (t == 0) s_den = s + EPS_ATTN;
    }

    const int m4 = (t & 15) * 4;         // 4 consecutive columns
    const int dg = t >> 4;               // row group 0..15
    size_t base = (size_t)bh * (Dc * Dc);
    float pn[4] = {0.0f, 0.0f, 0.0f, 0.0f};
    float vm0 = vs[m4 + 0], vm1 = vs[m4 + 1], vm2 = vs[m4 + 2], vm3 = vs[m4 + 3];
#pragma unroll
    for (int i = 0; i < 4; i++) {
        int d = dg + i * 16;
        size_t idx = base + (size_t)d * Dc + m4;
        float4 s4 = *(const float4*)&S_in[idx];
        float kd = ks[d];
        float4 sn;
        sn.x = fmaf(kd, vm0, s4.x);
        sn.y = fmaf(kd, vm1, s4.y);
        sn.z = fmaf(kd, vm2, s4.z);
        sn.w = fmaf(kd, vm3, s4.w);
        *(float4*)&S_out[idx] = sn;
        float qd = qs[d];
        pn[0] = fmaf(qd, sn.x, pn[0]);
        pn[1] = fmaf(qd, sn.y, pn[1]);
        pn[2] = fmaf(qd, sn.z, pn[2]);
        pn[3] = fmaf(qd, sn.w, pn[3]);
    }
    *(float4*)&rnum[dg * RSTR + m4] = *(float4*)pn;
    __syncthreads();

    if (t < Dc) {
        float num = 0.0f;
#pragma unroll
        for (int g = 0; g < 16; g++) num += rnum[g * RSTR + t];
        float av = num / s_den;
        __nv_bfloat16 vh = __float2bfloat16(av);
        ah[voff + t] = vh;
        al[voff + t] = __float2bfloat16(av - __bfloat162float(vh));
    }
}

// ---------------- LayerNorm (fuses split-K reduce + bias + residual) ---------
// Optionally also emits bf16 hi/lo of the output.
__global__ __launch_bounds__(256) void ln_kernel(
    const float* __restrict__ parts, int nparts, int partStride,
    const float* __restrict__ bias, const float* __restrict__ res,
    const float* __restrict__ g, const float* __restrict__ b,
    float* __restrict__ out,
    __nv_bfloat16* __restrict__ oh, __nv_bfloat16* __restrict__ ol)
{
    int row = blockIdx.x;                // 0..B-1
    int t   = threadIdx.x;               // 256 threads, 2 elems each
    float vv[2];
#pragma unroll
    for (int r = 0; r < 2; r++) {
        int c = t + 256 * r;
        size_t idx = (size_t)row * HIDc + c;
        float x = 0.0f;
        for (int p = 0; p < nparts; p++) x += parts[(size_t)p * partStride + idx];
        if (bias) x += bias[c];
        if (res)  x += res[idx];
        vv[r] = x;
    }
    float s = vv[0] + vv[1];
    float qsum = vv[0] * vv[0] + vv[1] * vv[1];
#pragma unroll
    for (int o = 16; o > 0; o >>= 1) {
        s    += __shfl_down_sync(0xffffffffu, s, o);
        qsum += __shfl_down_sync(0xffffffffu, qsum, o);
    }
    __shared__ float ss[8], sq[8];
    __shared__ float s_mean, s_rstd;
    int warp = t >> 5, lane = t & 31;
    if (lane == 0) { ss[warp] = s; sq[warp] = qsum; }
    __syncthreads();
    if (t == 0) {
        float S = 0.0f, Q = 0.0f;
#pragma unroll
        for (int w = 0; w < 8; w++) { S += ss[w]; Q += sq[w]; }
        float mean = S * (1.0f / (float)HIDc);
        float var  = Q * (1.0f / (float)HIDc) - mean * mean;
        s_mean = mean;
        s_rstd = rsqrtf(var + EPS_LN);
    }
    __syncthreads();
#pragma unroll
    for (int r = 0; r < 2; r++) {
        int c = t + 256 * r;
        size_t idx = (size_t)row * HIDc + c;
        float y = (vv[r] - s_mean) * s_rstd * g[c] + b[c];
        out[idx] = y;
        if (oh) {
            __nv_bfloat16 vh = __float2bfloat16(y);
            oh[idx] = vh;
            ol[idx] = __float2bfloat16(y - __bfloat162float(vh));
        }
    }
}

// ---------------- launcher ----------------------------------------------------
extern "C" void kernel_launch(void* const* d_in, const int* in_sizes, int n_in,
                              void* d_out, int out_size)
{
    (void)in_sizes; (void)n_in; (void)out_size;

    const int*   x     = (const int*)  d_in[0];
    const int*   pos   = (const int*)  d_in[1];
    const float* S     = (const float*)d_in[2];
    const float* Z     = (const float*)d_in[3];
    const float* emb   = (const float*)d_in[4];
    const float* Wq    = (const float*)d_in[5];
    const float* bq    = (const float*)d_in[6];
    const float* Wk    = (const float*)d_in[7];
    const float* bk    = (const float*)d_in[8];
    const float* Wv    = (const float*)d_in[9];
    const float* bv    = (const float*)d_in[10];
    const float* Wo    = (const float*)d_in[11];
    const float* bo    = (const float*)d_in[12];
    const float* W1    = (const float*)d_in[13];
    const float* b1    = (const float*)d_in[14];
    const float* W2    = (const float*)d_in[15];
    const float* b2    = (const float*)d_in[16];
    const float* ln1_g = (const float*)d_in[17];
    const float* ln1_b = (const float*)d_in[18];
    const float* ln2_g = (const float*)d_in[19];
    const float* ln2_b = (const float*)d_in[20];
    const float* lnf_g = (const float*)d_in[21];
    const float* lnf_b = (const float*)d_in[22];

    float* h_buf;          cudaGetSymbolAddress((void**)&h_buf,  g_h);
    __nv_bfloat16* hh;     cudaGetSymbolAddress((void**)&hh,     g_hh);
    __nv_bfloat16* hl;     cudaGetSymbolAddress((void**)&hl,     g_hl);
    __nv_bfloat16* ahp;    cudaGetSymbolAddress((void**)&ahp,    g_ah);
    __nv_bfloat16* alp;    cudaGetSymbolAddress((void**)&alp,    g_al);
    __nv_bfloat16* fh;     cudaGetSymbolAddress((void**)&fh,     g_fh);
    __nv_bfloat16* fl;     cudaGetSymbolAddress((void**)&fl,     g_fl);
    float* p_buf;          cudaGetSymbolAddress((void**)&p_buf,  g_part);
    float* qkvp;           cudaGetSymbolAddress((void**)&qkvp,   g_qkvp);
    __nv_bfloat16* whi;    cudaGetSymbolAddress((void**)&whi,    g_whi);
    __nv_bfloat16* wlo;    cudaGetSymbolAddress((void**)&wlo,    g_wlo);

    const size_t SZ = (size_t)Bc * Hc * Dc * Dc;  // 8388608 per layer
    const size_t ZZ = (size_t)Bc * Hc * Dc;       // 131072  per layer
    const size_t MN = (size_t)MNc;                // 131072

    float* out   = (float*)d_out;
    float* out_h = out;                           // [B,HID]
    float* out_S = out + MN;                      // [L,B,H,D,D]
    float* out_Z = out + MN + (size_t)Lc * SZ;    // [L,B,H,D]

    // weights -> bf16 hi/lo (once per call)
    split_weights_kernel<<<WTOT / 8 / 256, 256>>>(Wq, Wk, Wv, Wo, W1, W2, whi, wlo);

    // embedding + positional encoding (fp32 + hi/lo)
    embed_kernel<<<(Bc * HIDc) / 256, 256>>>(x, pos, emb, h_buf, hh, hl);

    for (int l = 0; l < Lc; l++) {
        const __nv_bfloat16* WLh = whi + (size_t)l * WPL;
        const __nv_bfloat16* WLl = wlo + (size_t)l * WPL;

        // QKV: split-K=2 per matrix -> 192 blocks, raw fp32 partials
        gemm_qkv_bf16_kernel<<<dim3(HIDc / 64, Bc / 64, 6), 128>>>(
            hh, hl, WLh, WLl, qkvp);

        // fused QKV-reduce + bias + elu(+1) + S/Z update + attention (hi/lo out)
        attn_state_kernel<<<Bc * Hc, 256>>>(
            S + (size_t)l * SZ, Z + (size_t)l * ZZ,
            qkvp, bq + l * HIDc, bk + l * HIDc, bv + l * HIDc,
            out_S + (size_t)l * SZ, out_Z + (size_t)l * ZZ, ahp, alp);

        // O projection, split-K=4 (128 blocks)
        gemm_bf16_kernel<<<dim3(HIDc / 64, Bc / 64, 4), 128>>>(
            ahp, alp, WLh + OFF_WO, WLl + OFF_WO, nullptr, p_buf,
            nullptr, nullptr, Bc, HIDc, HIDc, 0);

        // h = LN1(h + attn@Wo + bo)  (+ hi/lo for FF1)
        ln_kernel<<<Bc, 256>>>(p_buf, 4, (int)MN, bo + l * HIDc, h_buf,
                               ln1_g + l * HIDc, ln1_b + l * HIDc, h_buf, hh, hl);

        // FF1, split-K=1 (128 blocks), bias+relu+bf16 hi/lo fused in epilogue
        gemm_bf16_kernel<<<dim3(FFc / 64, Bc / 64, 1), 128>>>(
            hh, hl, WLh + OFF_W1, WLl + OFF_W1, b1 + l * FFc, nullptr,
            fh, fl, Bc, FFc, HIDc, 2);

        // FF2, split-K=8 (256 blocks)
        gemm_bf16_kernel<<<dim3(HIDc / 64, Bc / 64, 8), 128>>>(
            fh, fl, WLh + OFF_W2, WLl + OFF_W2, nullptr, p_buf,
            nullptr, nullptr, Bc, HIDc, FFc, 0);

        // h = LN2(h + ff)  (+ hi/lo for next layer's QKV)
        ln_kernel<<<Bc, 256>>>(p_buf, 8, (int)MN, b2 + l * HIDc, h_buf,
                               ln2_g + l * HIDc, ln2_b + l * HIDc, h_buf, hh, hl);
    }

    // final LayerNorm straight into d_out
    ln_kernel<<<Bc, 256>>>(h_buf, 1, 0, nullptr, nullptr, lnf_g, lnf_b, out_h,
                           nullptr, nullptr);
}

// round 14
// speedup vs baseline: 1.0734x; 1.0734x over previous
#include <cuda_runtime.h>
#include <cuda_bf16.h>
#include <mma.h>
#include <cstdint>
#include <cstddef>

using namespace nvcuda;

// Problem constants
#define Bc   256
#define HIDc 512
#define Hc   8
#define Dc   64
#define FFc  2048
#define Lc   6

#define EPS_ATTN 1e-6f
#define EPS_LN   1e-5f

#define MNc (Bc * HIDc)        // 131072
#define WPL 3145728            // weight elems per layer (Wq,Wk,Wv,Wo,W1,W2)
#define WTOT (Lc * WPL)        // 18874368
// per-layer weight offsets inside the packed hi/lo arrays
#define OFF_WQ 0
#define OFF_WK 262144
#define OFF_WV 524288
#define OFF_WO 786432
#define OFF_W1 1048576
#define OFF_W2 2097152

// ---------------- scratch (device globals; no allocations allowed) ----------
__device__ float          g_h[MNc];                 // fp32 h (residual path)
__device__ __nv_bfloat16  g_hh[MNc],  g_hl[MNc];    // h hi/lo
__device__ __nv_bfloat16  g_ah[MNc],  g_al[MNc];    // attn hi/lo
__device__ __nv_bfloat16  g_fh[Bc * FFc], g_fl[Bc * FFc];  // ff hi/lo
__device__ float          g_part[8 * MNc];          // split-K partials (O / FF1 / FF2)
__device__ float          g_qkvp[12 * MNc];         // QKV partials: slab = mat*4+split
__device__ __nv_bfloat16  g_whi[WTOT], g_wlo[WTOT]; // packed bf16 hi/lo weights

// ---------------- weight hi/lo split (runs once per call) -------------------
__global__ __launch_bounds__(256) void split_weights_kernel(
    const float* __restrict__ Wq, const float* __restrict__ Wk,
    const float* __restrict__ Wv, const float* __restrict__ Wo,
    const float* __restrict__ W1, const float* __restrict__ W2,
    __nv_bfloat16* __restrict__ hi, __nv_bfloat16* __restrict__ lo)
{
    size_t i = ((size_t)blockIdx.x * 256 + threadIdx.x) * 8;
    if (i >= WTOT) return;
    int l = (int)(i / WPL);
    size_t r = i - (size_t)l * WPL;
    const float* src;
    if      (r < 262144)  src = Wq + (size_t)l * 262144  + r;
    else if (r < 524288)  src = Wk + (size_t)l * 262144  + (r - 262144);
    else if (r < 786432)  src = Wv + (size_t)l * 262144  + (r - 524288);
    else if (r < 1048576) src = Wo + (size_t)l * 262144  + (r - 786432);
    else if (r < 2097152) src = W1 + (size_t)l * 1048576 + (r - 1048576);
    else                  src = W2 + (size_t)l * 1048576 + (r - 2097152);
    float4 v0 = *(const float4*)src;
    float4 v1 = *(const float4*)(src + 4);
    float xs[8] = {v0.x, v0.y, v0.z, v0.w, v1.x, v1.y, v1.z, v1.w};
    __align__(16) __nv_bfloat16 th[8], tl[8];
#pragma unroll
    for (int e = 0; e < 8; e++) {
        __nv_bfloat16 h = __float2bfloat16(xs[e]);
        th[e] = h;
        tl[e] = __float2bfloat16(xs[e] - __bfloat162float(h));
    }
    *(float4*)&hi[i] = *(float4*)th;
    *(float4*)&lo[i] = *(float4*)tl;
}

// ---------------- embedding + positional encoding ---------------------------
__global__ __launch_bounds__(256) void embed_kernel(
    const int* __restrict__ x, const int* __restrict__ pos_p,
    const float* __restrict__ emb, float* __restrict__ h,
    __nv_bfloat16* __restrict__ hh, __nv_bfloat16* __restrict__ hl)
{
    int i = blockIdx.x * 256 + threadIdx.x;           // 0 .. B*HID-1
    int b = i >> 9;
    int c = i & 511;
    float posf = (float)(*pos_p);
    int j2 = c & ~1;                                   // 2*j
    float e = (float)j2 * (1.0f / (float)HIDc);
    float ang = posf * powf(10000.0f, -e);
    float pe = (c & 1) ? cosf(ang) : sinf(ang);
    float v = emb[(size_t)x[b] * HIDc + c] + pe;
    h[i] = v;
    __nv_bfloat16 vh = __float2bfloat16(v);
    hh[i] = vh;
    hl[i] = __float2bfloat16(v - __bfloat162float(vh));
}

// ---------------- bf16 hi/lo tensor-core GEMM (256 threads, 8 warps) --------
// C[M,N] = A[M,K] @ W[K,N] over k in [k0, k0+kLen); 3 bf16 MMAs per hi/lo pair.
// 64x64 tile, BK=32, warp grid 4x2 (warp tile 16x32), smem ping-pong.
#define BKb  32
#define LDAb 40
#define LDBb 72

__device__ __forceinline__ void gemm_bf16_body(
    const __nv_bfloat16* __restrict__ Ah, const __nv_bfloat16* __restrict__ Al,
    const __nv_bfloat16* __restrict__ Wh, const __nv_bfloat16* __restrict__ Wl,
    const float* __restrict__ bias, float* __restrict__ C,
    int N, int K, int k0, int kLen, int act)
{
    __shared__ __align__(16) __nv_bfloat16 sA[2][2][64][LDAb];  // [buf][hi/lo]
    __shared__ __align__(16) __nv_bfloat16 sB[2][2][BKb][LDBb];

    const int tid   = threadIdx.x;           // 256 threads
    const int warp  = tid >> 5;
    const int wm    = warp & 3;              // 4 m-slices of 16
    const int wn    = warp >> 2;             // 2 n-slices of 32
    const int row0  = blockIdx.y * 64;
    const int col0  = blockIdx.x * 64;

    const __nv_bfloat16* Agh = Ah + (size_t)row0 * K + k0;
    const __nv_bfloat16* Agl = Al + (size_t)row0 * K + k0;
    const __nv_bfloat16* Wgh = Wh + (size_t)k0 * N + col0;
    const __nv_bfloat16* Wgl = Wl + (size_t)k0 * N + col0;

    // global slots: A tile 64x32 bf16 = 256 float4 per (hi|lo); same for B.
    const int ar  = tid >> 2, ac8 = (tid & 3) * 8;
    const int br  = tid >> 3, bc8 = (tid & 7) * 8;

    float4 pAh, pAl, pBh, pBl;
    pAh = *(const float4*)(Agh + (size_t)ar * K + ac8);
    pAl = *(const float4*)(Agl + (size_t)ar * K + ac8);
    pBh = *(const float4*)(Wgh + (size_t)br * N + bc8);
    pBl = *(const float4*)(Wgl + (size_t)br * N + bc8);

    *(float4*)&sA[0][0][ar][ac8] = pAh;
    *(float4*)&sA[0][1][ar][ac8] = pAl;
    *(float4*)&sB[0][0][br][bc8] = pBh;
    *(float4*)&sB[0][1][br][bc8] = pBl;
    __syncthreads();

    wmma::fragment<wmma::accumulator, 16, 16, 16, float> acc[2];
#pragma unroll
    for (int ni = 0; ni < 2; ni++) wmma::fill_fragment(acc[ni], 0.0f);

    const int ntiles = kLen / BKb;
    for (int t = 0; t < ntiles; t++) {
        const int cur = t & 1, nxt = cur ^ 1;

        if (t + 1 < ntiles) {                // prefetch next tile into regs
            const __nv_bfloat16* Agh2 = Agh + (t + 1) * BKb;
            const __nv_bfloat16* Agl2 = Agl + (t + 1) * BKb;
            const __nv_bfloat16* Wgh2 = Wgh + (size_t)(t + 1) * BKb * N;
            const __nv_bfloat16* Wgl2 = Wgl + (size_t)(t + 1) * BKb * N;
            pAh = *(const float4*)(Agh2 + (size_t)ar * K + ac8);
            pAl = *(const float4*)(Agl2 + (size_t)ar * K + ac8);
            pBh = *(const float4*)(Wgh2 + (size_t)br * N + bc8);
            pBl = *(const float4*)(Wgl2 + (size_t)br * N + bc8);
        }

#pragma unroll
        for (int ks = 0; ks < 2; ks++) {
            wmma::fragment<wmma::matrix_a, 16, 16, 16, __nv_bfloat16, wmma::row_major> a_hi, a_lo;
            wmma::fragment<wmma::matrix_b, 16, 16, 16, __nv_bfloat16, wmma::row_major> b_hi[2], b_lo[2];
            int mrow = wm * 16;
            wmma::load_matrix_sync(a_hi, &sA[cur][0][mrow][ks * 16], LDAb);
            wmma::load_matrix_sync(a_lo, &sA[cur][1][mrow][ks * 16], LDAb);
#pragma unroll
            for (int ni = 0; ni < 2; ni++) {
                int ncol = wn * 32 + ni * 16;
                wmma::load_matrix_sync(b_hi[ni], &sB[cur][0][ks * 16][ncol], LDBb);
                wmma::load_matrix_sync(b_lo[ni], &sB[cur][1][ks * 16][ncol], LDBb);
            }
#pragma unroll
            for (int ni = 0; ni < 2; ni++) {
                wmma::mma_sync(acc[ni], a_hi, b_hi[ni], acc[ni]);
                wmma::mma_sync(acc[ni], a_lo, b_hi[ni], acc[ni]);
                wmma::mma_sync(acc[ni], a_hi, b_lo[ni], acc[ni]);
            }
        }

        if (t + 1 < ntiles) {                // commit prefetched tile
            *(float4*)&sA[nxt][0][ar][ac8] = pAh;
            *(float4*)&sA[nxt][1][ar][ac8] = pAl;
            *(float4*)&sB[nxt][0][br][bc8] = pBh;
            *(float4*)&sB[nxt][1][br][bc8] = pBl;
        }
        __syncthreads();
    }

    // epilogue: fragments -> smem C tile (aliases sA) -> bias/act -> gmem
    float* cT = (float*)&sA[0][0][0][0];     // 64x64 fp32 = 16KB
#pragma unroll
    for (int ni = 0; ni < 2; ni++)
        wmma::store_matrix_sync(&cT[(wm * 16) * 64 + wn * 32 + ni * 16],
                                acc[ni], 64, wmma::mem_row_major);
    __syncthreads();

#pragma unroll
    for (int u = 0; u < 4; u++) {
        int s = tid + u * 256;               // 1024 float4 slots
        int r = s >> 4, c4 = (s & 15) * 4;
        float4 vv = *(const float4*)&cT[r * 64 + c4];
        float* pv = (float*)&vv;
        if (bias) {
#pragma unroll
            for (int e = 0; e < 4; e++) pv[e] += bias[col0 + c4 + e];
        }
        if (act == 2) {
#pragma unroll
            for (int e = 0; e < 4; e++) pv[e] = fmaxf(pv[e], 0.0f);
        }
        *(float4*)&C[(size_t)(row0 + r) * N + col0 + c4] = vv;
    }
}

// Generic GEMM; grid.z = split-K count; split z writes partial slab z of C.
__global__ __launch_bounds__(256) void gemm_bf16_kernel(
    const __nv_bfloat16* __restrict__ Ah, const __nv_bfloat16* __restrict__ Al,
    const __nv_bfloat16* __restrict__ Wh, const __nv_bfloat16* __restrict__ Wl,
    const float* __restrict__ bias, float* __restrict__ C,
    int M, int N, int K, int act)
{
    int kLen = K / gridDim.z;
    int k0   = blockIdx.z * kLen;
    C += (size_t)blockIdx.z * M * N;
    gemm_bf16_body(Ah, Al, Wh, Wl, bias, C, N, K, k0, kLen, act);
}

// QKV GEMM, split-K=4 per matrix: grid.z in 0..11, mat = z>>2, split = z&3.
__global__ __launch_bounds__(256) void gemm_qkv_bf16_kernel(
    const __nv_bfloat16* __restrict__ Ah, const __nv_bfloat16* __restrict__ Al,
    const __nv_bfloat16* __restrict__ WLh, const __nv_bfloat16* __restrict__ WLl,
    float* __restrict__ qkvp)
{
    int mat   = blockIdx.z >> 2;
    int split = blockIdx.z & 3;
    const __nv_bfloat16* Wh = WLh + (size_t)mat * 262144;
    const __nv_bfloat16* Wl = WLl + (size_t)mat * 262144;
    float* C = qkvp + (size_t)blockIdx.z * MNc;
    gemm_bf16_body(Ah, Al, Wh, Wl, nullptr, C, HIDc, HIDc,
                   split * (HIDc / 4), HIDc / 4, 0);
}

// FF1 split-K=2 reduce + bias + relu -> ff hi/lo bf16
__global__ __launch_bounds__(256) void reduce_bias_relu_kernel(
    const float* __restrict__ p, const float* __restrict__ bias,
    __nv_bfloat16* __restrict__ oh, __nv_bfloat16* __restrict__ ol)
{
    int i4 = blockIdx.x * 256 + threadIdx.x;      // float4 index over B*FF/4
    int i  = i4 * 4;
    int c  = i & (FFc - 1);
    const size_t STR = (size_t)Bc * FFc;
    float4 a = *(const float4*)&p[i];
    float4 b = *(const float4*)&p[STR + i];
    float xs[4] = {a.x + b.x, a.y + b.y, a.z + b.z, a.w + b.w};
    __align__(8) __nv_bfloat16 th[4], tl[4];
#pragma unroll
    for (int e = 0; e < 4; e++) {
        float v = fmaxf(xs[e] + bias[c + e], 0.0f);
        __nv_bfloat16 vh = __float2bfloat16(v);
        th[e] = vh;
        tl[e] = __float2bfloat16(v - __bfloat162float(vh));
    }
    *(uint2*)&oh[i] = *(uint2*)th;
    *(uint2*)&ol[i] = *(uint2*)tl;
}

// ---------------- fused linear-attention state update ------------------------
// One block per (b,h). Fuses: QKV split-K(4) reduce + bias + elu(+1);
// S_out = S + k v^T, num = q . S_out, den = q.(Z+k)+eps, attn = num/den (hi/lo).
// Batched float4 loads on the S stream (MLP=4), then fma+store.
#define RSTR 68

__global__ __launch_bounds__(256) void attn_state_kernel(
    const float* __restrict__ S_in, const float* __restrict__ Z_in,
    const float* __restrict__ qkvp,
    const float* __restrict__ bq, const float* __restrict__ bk,
    const float* __restrict__ bv,
    float* __restrict__ S_out, float* __restrict__ Z_out,
    __nv_bfloat16* __restrict__ ah, __nv_bfloat16* __restrict__ al)
{
    int bh = blockIdx.x;                 // 0 .. B*H-1
    int t  = threadIdx.x;                // 256 threads
    __shared__ float qs[Dc], ks[Dc], vs[Dc];
    __shared__ float rnum[16 * RSTR];
    __shared__ float red64[Dc];
    __shared__ float s_den;

    int voff = bh * Dc;                  // == b*HID + h*D
    if (t < Dc) {
        int c = ((bh & (Hc - 1)) << 6) + t;          // column within HID
        float qq = bq[c], kk = bk[c], vv = bv[c];
#pragma unroll
        for (int p = 0; p < 4; p++) {
            qq += qkvp[(size_t)p * MNc + voff + t];
            kk += qkvp[(size_t)(4 + p) * MNc + voff + t];
            vv += qkvp[(size_t)(8 + p) * MNc + voff + t];
        }
        qq = (qq > 0.0f) ? (qq + 1.0f) : expf(qq);   // elu(x)+1
        kk = (kk > 0.0f) ? (kk + 1.0f) : expf(kk);
        qs[t] = qq; ks[t] = kk; vs[t] = vv;
        float zn = Z_in[voff + t] + kk;
        Z_out[voff + t] = zn;
        red64[t] = qq * zn;
    }
    __syncthreads();
    if (t < 32) {
        float s = red64[t] + red64[t + 32];
#pragma unroll
        for (int o = 16; o > 0; o >>= 1) s += __shfl_down_sync(0xffffffffu, s, o);
        if (t == 0) s_den = s + EPS_ATTN;
    }

    const int m4 = (t & 15) * 4;         // 4 consecutive columns
    const int dg = t >> 4;               // row group 0..15
    size_t base = (size_t)bh * (Dc * Dc) + (size_t)dg * Dc + m4;

    // batched loads (4 independent LDG.128 in flight)
    float4 s4[4];
#pragma unroll
    for (int i = 0; i < 4; i++) s4[i] = *(const float4*)&S_in[base + (size_t)i * 16 * Dc];

    float vm0 = vs[m4 + 0], vm1 = vs[m4 + 1], vm2 = vs[m4 + 2], vm3 = vs[m4 + 3];
    float pn[4] = {0.0f, 0.0f, 0.0f, 0.0f};
#pragma unroll
    for (int i = 0; i < 4; i++) {
        int d = dg + i * 16;
        float kd = ks[d], qd = qs[d];
        float4 sn;
        sn.x = fmaf(kd, vm0, s4[i].x);
        sn.y = fmaf(kd, vm1, s4[i].y);
        sn.z = fmaf(kd, vm2, s4[i].z);
        sn.w = fmaf(kd, vm3, s4[i].w);
        *(float4*)&S_out[base + (size_t)i * 16 * Dc] = sn;
        pn[0] = fmaf(qd, sn.x, pn[0]);
        pn[1] = fmaf(qd, sn.y, pn[1]);
        pn[2] = fmaf(qd, sn.z, pn[2]);
        pn[3] = fmaf(qd, sn.w, pn[3]);
    }
    *(float4*)&rnum[dg * RSTR + m4] = *(float4*)pn;
    __syncthreads();

    if (t < Dc) {
        float num = 0.0f;
#pragma unroll
        for (int g = 0; g < 16; g++) num += rnum[g * RSTR + t];
        float av = num / s_den;
        __nv_bfloat16 vh = __float2bfloat16(av);
        ah[voff + t] = vh;
        al[voff + t] = __float2bfloat16(av - __bfloat162float(vh));
    }
}

// ---------------- LayerNorm (fuses split-K reduce + bias + residual) ---------
__global__ __launch_bounds__(256) void ln_kernel(
    const float* __restrict__ parts, int nparts, int partStride,
    const float* __restrict__ bias, const float* __restrict__ res,
    const float* __restrict__ g, const float* __restrict__ b,
    float* __restrict__ out,
    __nv_bfloat16* __restrict__ oh, __nv_bfloat16* __restrict__ ol)
{
    int row = blockIdx.x;                // 0..B-1
    int t   = threadIdx.x;               // 256 threads, 2 elems each
    float vv[2];
#pragma unroll
    for (int r = 0; r < 2; r++) {
        int c = t + 256 * r;
        size_t idx = (size_t)row * HIDc + c;
        float x = 0.0f;
        for (int p = 0; p < nparts; p++) x += parts[(size_t)p * partStride + idx];
        if (bias) x += bias[c];
        if (res)  x += res[idx];
        vv[r] = x;
    }
    float s = vv[0] + vv[1];
    float qsum = vv[0] * vv[0] + vv[1] * vv[1];
#pragma unroll
    for (int o = 16; o > 0; o >>= 1) {
        s    += __shfl_down_sync(0xffffffffu, s, o);
        qsum += __shfl_down_sync(0xffffffffu, qsum, o);
    }
    __shared__ float ss[8], sq[8];
    __shared__ float s_mean, s_rstd;
    int warp = t >> 5, lane = t & 31;
    if (lane == 0) { ss[warp] = s; sq[warp] = qsum; }
    __syncthreads();
    if (t == 0) {
        float S = 0.0f, Q = 0.0f;
#pragma unroll
        for (int w = 0; w < 8; w++) { S += ss[w]; Q += sq[w]; }
        float mean = S * (1.0f / (float)HIDc);
        float var  = Q * (1.0f / (float)HIDc) - mean * mean;
        s_mean = mean;
        s_rstd = rsqrtf(var + EPS_LN);
    }
    __syncthreads();
#pragma unroll
    for (int r = 0; r < 2; r++) {
        int c = t + 256 * r;
        size_t idx = (size_t)row * HIDc + c;
        float y = (vv[r] - s_mean) * s_rstd * g[c] + b[c];
        out[idx] = y;
        if (oh) {
            __nv_bfloat16 vh = __float2bfloat16(y);
            oh[idx] = vh;
            ol[idx] = __float2bfloat16(y - __bfloat162float(vh));
        }
    }
}

// ---------------- launcher ----------------------------------------------------
extern "C" void kernel_launch(void* const* d_in, const int* in_sizes, int n_in,
                              void* d_out, int out_size)
{
    (void)in_sizes; (void)n_in; (void)out_size;

    const int*   x     = (const int*)  d_in[0];
    const int*   pos   = (const int*)  d_in[1];
    const float* S     = (const float*)d_in[2];
    const float* Z     = (const float*)d_in[3];
    const float* emb   = (const float*)d_in[4];
    const float* Wq    = (const float*)d_in[5];
    const float* bq    = (const float*)d_in[6];
    const float* Wk    = (const float*)d_in[7];
    const float* bk    = (const float*)d_in[8];
    const float* Wv    = (const float*)d_in[9];
    const float* bv    = (const float*)d_in[10];
    const float* Wo    = (const float*)d_in[11];
    const float* bo    = (const float*)d_in[12];
    const float* W1    = (const float*)d_in[13];
    const float* b1    = (const float*)d_in[14];
    const float* W2    = (const float*)d_in[15];
    const float* b2    = (const float*)d_in[16];
    const float* ln1_g = (const float*)d_in[17];
    const float* ln1_b = (const float*)d_in[18];
    const float* ln2_g = (const float*)d_in[19];
    const float* ln2_b = (const float*)d_in[20];
    const float* lnf_g = (const float*)d_in[21];
    const float* lnf_b = (const float*)d_in[22];

    float* h_buf;          cudaGetSymbolAddress((void**)&h_buf,  g_h);
    __nv_bfloat16* hh;     cudaGetSymbolAddress((void**)&hh,     g_hh);
    __nv_bfloat16* hl;     cudaGetSymbolAddress((void**)&hl,     g_hl);
    __nv_bfloat16* ahp;    cudaGetSymbolAddress((void**)&ahp,    g_ah);
    __nv_bfloat16* alp;    cudaGetSymbolAddress((void**)&alp,    g_al);
    __nv_bfloat16* fh;     cudaGetSymbolAddress((void**)&fh,     g_fh);
    __nv_bfloat16* fl;     cudaGetSymbolAddress((void**)&fl,     g_fl);
    float* p_buf;          cudaGetSymbolAddress((void**)&p_buf,  g_part);
    float* qkvp;           cudaGetSymbolAddress((void**)&qkvp,   g_qkvp);
    __nv_bfloat16* whi;    cudaGetSymbolAddress((void**)&whi,    g_whi);
    __nv_bfloat16* wlo;    cudaGetSymbolAddress((void**)&wlo,    g_wlo);

    const size_t SZ = (size_t)Bc * Hc * Dc * Dc;  // 8388608 per layer
    const size_t ZZ = (size_t)Bc * Hc * Dc;       // 131072  per layer
    const size_t MN = (size_t)MNc;                // 131072

    float* out   = (float*)d_out;
    float* out_h = out;                           // [B,HID]
    float* out_S = out + MN;                      // [L,B,H,D,D]
    float* out_Z = out + MN + (size_t)Lc * SZ;    // [L,B,H,D]

    // weights -> bf16 hi/lo (once per call)
    split_weights_kernel<<<WTOT / 8 / 256, 256>>>(Wq, Wk, Wv, Wo, W1, W2, whi, wlo);

    // embedding + positional encoding (fp32 + hi/lo)
    embed_kernel<<<(Bc * HIDc) / 256, 256>>>(x, pos, emb, h_buf, hh, hl);

    for (int l = 0; l < Lc; l++) {
        const __nv_bfloat16* WLh = whi + (size_t)l * WPL;
        const __nv_bfloat16* WLl = wlo + (size_t)l * WPL;

        // QKV: split-K=4 per matrix -> 384 blocks, raw fp32 partials
        gemm_qkv_bf16_kernel<<<dim3(HIDc / 64, Bc / 64, 12), 256>>>(
            hh, hl, WLh, WLl, qkvp);

        // fused QKV-reduce + bias + elu(+1) + S/Z update + attention (hi/lo out)
        attn_state_kernel<<<Bc * Hc, 256>>>(
            S + (size_t)l * SZ, Z + (size_t)l * ZZ,
            qkvp, bq + l * HIDc, bk + l * HIDc, bv + l * HIDc,
            out_S + (size_t)l * SZ, out_Z + (size_t)l * ZZ, ahp, alp);

        // O projection, split-K=8 (256 blocks)
        gemm_bf16_kernel<<<dim3(HIDc / 64, Bc / 64, 8), 256>>>(
            ahp, alp, WLh + OFF_WO, WLl + OFF_WO, nullptr, p_buf,
            Bc, HIDc, HIDc, 0);

        // h = LN1(h + attn@Wo + bo)  (+ hi/lo for FF1)
        ln_kernel<<<Bc, 256>>>(p_buf, 8, (int)MN, bo + l * HIDc, h_buf,
                               ln1_g + l * HIDc, ln1_b + l * HIDc, h_buf, hh, hl);

        // FF1, split-K=2 (256 blocks); bias+relu+hi/lo in reduce
        gemm_bf16_kernel<<<dim3(FFc / 64, Bc / 64, 2), 256>>>(
            hh, hl, WLh + OFF_W1, WLl + OFF_W1, nullptr, p_buf,
            Bc, FFc, HIDc, 0);
        reduce_bias_relu_kernel<<<(Bc * FFc / 4) / 256, 256>>>(
            p_buf, b1 + l * FFc, fh, fl);

        // FF2, split-K=8 (256 blocks)
        gemm_bf16_kernel<<<dim3(HIDc / 64, Bc / 64, 8), 256>>>(
            fh, fl, WLh + OFF_W2, WLl + OFF_W2, nullptr, p_buf,
            Bc, HIDc, FFc, 0);

        // h = LN2(h + ff)  (+ hi/lo for next layer's QKV)
        ln_kernel<<<Bc, 256>>>(p_buf, 8, (int)MN, b2 + l * HIDc, h_buf,
                               ln2_g + l * HIDc, ln2_b + l * HIDc, h_buf, hh, hl);
    }

    // final LayerNorm straight into d_out
    ln_kernel<<<Bc, 256>>>(h_buf, 1, 0, nullptr, nullptr, lnf_g, lnf_b, out_h,
                           nullptr, nullptr);
}

// round 15
// speedup vs baseline: 1.0832x; 1.0091x over previous
#include <cuda_runtime.h>
#include <cuda_bf16.h>
#include <mma.h>
#include <cstdint>
#include <cstddef>

using namespace nvcuda;

// Problem constants
#define Bc   256
#define HIDc 512
#define Hc   8
#define Dc   64
#define FFc  2048
#define Lc   6

#define EPS_ATTN 1e-6f
#define EPS_LN   1e-5f

#define MNc (Bc * HIDc)        // 131072
#define WPL 3145728            // weight elems per layer (Wq,Wk,Wv,Wo,W1,W2)
#define WTOT (Lc * WPL)        // 18874368
// per-layer weight offsets inside the packed hi/lo arrays
#define OFF_WQ 0
#define OFF_WK 262144
#define OFF_WV 524288
#define OFF_WO 786432
#define OFF_W1 1048576
#define OFF_W2 2097152

// ---------------- scratch (device globals; no allocations allowed) ----------
__device__ float          g_h[MNc];                 // fp32 h (residual path)
__device__ __nv_bfloat16  g_hh[MNc],  g_hl[MNc];    // h hi/lo
__device__ __nv_bfloat16  g_ah[MNc],  g_al[MNc];    // attn hi/lo
__device__ __nv_bfloat16  g_fh[Bc * FFc], g_fl[Bc * FFc];  // ff hi/lo
__device__ float          g_part[8 * MNc];          // split-K partials (O / FF1 / FF2)
__device__ float          g_qkvp[12 * MNc];         // QKV partials: slab = mat*4+split
__device__ __nv_bfloat16  g_whi[WTOT], g_wlo[WTOT]; // packed bf16 hi/lo weights

// ---------------- weight hi/lo split (runs once per call) -------------------
__global__ __launch_bounds__(256) void split_weights_kernel(
    const float* __restrict__ Wq, const float* __restrict__ Wk,
    const float* __restrict__ Wv, const float* __restrict__ Wo,
    const float* __restrict__ W1, const float* __restrict__ W2,
    __nv_bfloat16* __restrict__ hi, __nv_bfloat16* __restrict__ lo)
{
    size_t i = ((size_t)blockIdx.x * 256 + threadIdx.x) * 8;
    if (i >= WTOT) return;
    int l = (int)(i / WPL);
    size_t r = i - (size_t)l * WPL;
    const float* src;
    if      (r < 262144)  src = Wq + (size_t)l * 262144  + r;
    else if (r < 524288)  src = Wk + (size_t)l * 262144  + (r - 262144);
    else if (r < 786432)  src = Wv + (size_t)l * 262144  + (r - 524288);
    else if (r < 1048576) src = Wo + (size_t)l * 262144  + (r - 786432);
    else if (r < 2097152) src = W1 + (size_t)l * 1048576 + (r - 1048576);
    else                  src = W2 + (size_t)l * 1048576 + (r - 2097152);
    float4 v0 = *(const float4*)src;
    float4 v1 = *(const float4*)(src + 4);
    float xs[8] = {v0.x, v0.y, v0.z, v0.w, v1.x, v1.y, v1.z, v1.w};
    __align__(16) __nv_bfloat16 th[8], tl[8];
#pragma unroll
    for (int e = 0; e < 8; e++) {
        __nv_bfloat16 h = __float2bfloat16(xs[e]);
        th[e] = h;
        tl[e] = __float2bfloat16(xs[e] - __bfloat162float(h));
    }
    *(float4*)&hi[i] = *(float4*)th;
    *(float4*)&lo[i] = *(float4*)tl;
}

// ---------------- embedding + positional encoding ---------------------------
__global__ __launch_bounds__(256) void embed_kernel(
    const int* __restrict__ x, const int* __restrict__ pos_p,
    const float* __restrict__ emb, float* __restrict__ h,
    __nv_bfloat16* __restrict__ hh, __nv_bfloat16* __restrict__ hl)
{
    int i = blockIdx.x * 256 + threadIdx.x;           // 0 .. B*HID-1
    int b = i >> 9;
    int c = i & 511;
    float posf = (float)(*pos_p);
    int j2 = c & ~1;                                   // 2*j
    float e = (float)j2 * (1.0f / (float)HIDc);
    float ang = posf * powf(10000.0f, -e);
    float pe = (c & 1) ? cosf(ang) : sinf(ang);
    float v = emb[(size_t)x[b] * HIDc + c] + pe;
    h[i] = v;
    __nv_bfloat16 vh = __float2bfloat16(v);
    hh[i] = vh;
    hl[i] = __float2bfloat16(v - __bfloat162float(vh));
}

// ---------------- bf16 hi/lo tensor-core GEMM (256 threads, 8 warps) --------
// C[M,N] = A[M,K] @ W[K,N] over k in [k0, k0+kLen); 3 bf16 MMAs per hi/lo pair.
// 64x64 tile, BK=32, warp grid 4x2 (warp tile 16x32), smem ping-pong.
#define BKb  32
#define LDAb 40
#define LDBb 72

__device__ __forceinline__ void gemm_bf16_body(
    const __nv_bfloat16* __restrict__ Ah, const __nv_bfloat16* __restrict__ Al,
    const __nv_bfloat16* __restrict__ Wh, const __nv_bfloat16* __restrict__ Wl,
    const float* __restrict__ bias, float* __restrict__ C,
    int N, int K, int k0, int kLen, int act)
{
    __shared__ __align__(16) __nv_bfloat16 sA[2][2][64][LDAb];  // [buf][hi/lo]
    __shared__ __align__(16) __nv_bfloat16 sB[2][2][BKb][LDBb];

    const int tid   = threadIdx.x;           // 256 threads
    const int warp  = tid >> 5;
    const int wm    = warp & 3;              // 4 m-slices of 16
    const int wn    = warp >> 2;             // 2 n-slices of 32
    const int row0  = blockIdx.y * 64;
    const int col0  = blockIdx.x * 64;

    const __nv_bfloat16* Agh = Ah + (size_t)row0 * K + k0;
    const __nv_bfloat16* Agl = Al + (size_t)row0 * K + k0;
    const __nv_bfloat16* Wgh = Wh + (size_t)k0 * N + col0;
    const __nv_bfloat16* Wgl = Wl + (size_t)k0 * N + col0;

    // global slots: A tile 64x32 bf16 = 256 float4 per (hi|lo); same for B.
    const int ar  = tid >> 2, ac8 = (tid & 3) * 8;
    const int br  = tid >> 3, bc8 = (tid & 7) * 8;

    float4 pAh, pAl, pBh, pBl;
    pAh = *(const float4*)(Agh + (size_t)ar * K + ac8);
    pAl = *(const float4*)(Agl + (size_t)ar * K + ac8);
    pBh = *(const float4*)(Wgh + (size_t)br * N + bc8);
    pBl = *(const float4*)(Wgl + (size_t)br * N + bc8);

    *(float4*)&sA[0][0][ar][ac8] = pAh;
    *(float4*)&sA[0][1][ar][ac8] = pAl;
    *(float4*)&sB[0][0][br][bc8] = pBh;
    *(float4*)&sB[0][1][br][bc8] = pBl;
    __syncthreads();

    wmma::fragment<wmma::accumulator, 16, 16, 16, float> acc[2];
#pragma unroll
    for (int ni = 0; ni < 2; ni++) wmma::fill_fragment(acc[ni], 0.0f);

    const int ntiles = kLen / BKb;
    for (int t = 0; t < ntiles; t++) {
        const int cur = t & 1, nxt = cur ^ 1;

        if (t + 1 < ntiles) {                // prefetch next tile into regs
            const __nv_bfloat16* Agh2 = Agh + (t + 1) * BKb;
            const __nv_bfloat16* Agl2 = Agl + (t + 1) * BKb;
            const __nv_bfloat16* Wgh2 = Wgh + (size_t)(t + 1) * BKb * N;
            const __nv_bfloat16* Wgl2 = Wgl + (size_t)(t + 1) * BKb * N;
            pAh = *(const float4*)(Agh2 + (size_t)ar * K + ac8);
            pAl = *(const float4*)(Agl2 + (size_t)ar * K + ac8);
            pBh = *(const float4*)(Wgh2 + (size_t)br * N + bc8);
            pBl = *(const float4*)(Wgl2 + (size_t)br * N + bc8);
        }

#pragma unroll
        for (int ks = 0; ks < 2; ks++) {
            wmma::fragment<wmma::matrix_a, 16, 16, 16, __nv_bfloat16, wmma::row_major> a_hi, a_lo;
            wmma::fragment<wmma::matrix_b, 16, 16, 16, __nv_bfloat16, wmma::row_major> b_hi[2], b_lo[2];
            int mrow = wm * 16;
            wmma::load_matrix_sync(a_hi, &sA[cur][0][mrow][ks * 16], LDAb);
            wmma::load_matrix_sync(a_lo, &sA[cur][1][mrow][ks * 16], LDAb);
#pragma unroll
            for (int ni = 0; ni < 2; ni++) {
                int ncol = wn * 32 + ni * 16;
                wmma::load_matrix_sync(b_hi[ni], &sB[cur][0][ks * 16][ncol], LDBb);
                wmma::load_matrix_sync(b_lo[ni], &sB[cur][1][ks * 16][ncol], LDBb);
            }
#pragma unroll
            for (int ni = 0; ni < 2; ni++) {
                wmma::mma_sync(acc[ni], a_hi, b_hi[ni], acc[ni]);
                wmma::mma_sync(acc[ni], a_lo, b_hi[ni], acc[ni]);
                wmma::mma_sync(acc[ni], a_hi, b_lo[ni], acc[ni]);
            }
        }

        if (t + 1 < ntiles) {                // commit prefetched tile
            *(float4*)&sA[nxt][0][ar][ac8] = pAh;
            *(float4*)&sA[nxt][1][ar][ac8] = pAl;
            *(float4*)&sB[nxt][0][br][bc8] = pBh;
            *(float4*)&sB[nxt][1][br][bc8] = pBl;
        }
        __syncthreads();
    }

    // epilogue: fragments -> smem C tile (aliases sA) -> bias/act -> gmem
    float* cT = (float*)&sA[0][0][0][0];     // 64x64 fp32 = 16KB
#pragma unroll
    for (int ni = 0; ni < 2; ni++)
        wmma::store_matrix_sync(&cT[(wm * 16) * 64 + wn * 32 + ni * 16],
                                acc[ni], 64, wmma::mem_row_major);
    __syncthreads();

#pragma unroll
    for (int u = 0; u < 4; u++) {
        int s = tid + u * 256;               // 1024 float4 slots
        int r = s >> 4, c4 = (s & 15) * 4;
        float4 vv = *(const float4*)&cT[r * 64 + c4];
        float* pv = (float*)&vv;
        if (bias) {
#pragma unroll
            for (int e = 0; e < 4; e++) pv[e] += bias[col0 + c4 + e];
        }
        if (act == 2) {
#pragma unroll
            for (int e = 0; e < 4; e++) pv[e] = fmaxf(pv[e], 0.0f);
        }
        *(float4*)&C[(size_t)(row0 + r) * N + col0 + c4] = vv;
    }
}

// Generic GEMM; grid.z = split-K count; split z writes partial slab z of C.
__global__ __launch_bounds__(256) void gemm_bf16_kernel(
    const __nv_bfloat16* __restrict__ Ah, const __nv_bfloat16* __restrict__ Al,
    const __nv_bfloat16* __restrict__ Wh, const __nv_bfloat16* __restrict__ Wl,
    const float* __restrict__ bias, float* __restrict__ C,
    int M, int N, int K, int act)
{
    int kLen = K / gridDim.z;
    int k0   = blockIdx.z * kLen;
    C += (size_t)blockIdx.z * M * N;
    gemm_bf16_body(Ah, Al, Wh, Wl, bias, C, N, K, k0, kLen, act);
}

// QKV GEMM, split-K=4 per matrix: grid.z in 0..11, mat = z>>2, split = z&3.
__global__ __launch_bounds__(256) void gemm_qkv_bf16_kernel(
    const __nv_bfloat16* __restrict__ Ah, const __nv_bfloat16* __restrict__ Al,
    const __nv_bfloat16* __restrict__ WLh, const __nv_bfloat16* __restrict__ WLl,
    float* __restrict__ qkvp)
{
    int mat   = blockIdx.z >> 2;
    int split = blockIdx.z & 3;
    const __nv_bfloat16* Wh = WLh + (size_t)mat * 262144;
    const __nv_bfloat16* Wl = WLl + (size_t)mat * 262144;
    float* C = qkvp + (size_t)blockIdx.z * MNc;
    gemm_bf16_body(Ah, Al, Wh, Wl, nullptr, C, HIDc, HIDc,
                   split * (HIDc / 4), HIDc / 4, 0);
}

// FF1 split-K=2 reduce + bias + relu -> ff hi/lo bf16
__global__ __launch_bounds__(256) void reduce_bias_relu_kernel(
    const float* __restrict__ p, const float* __restrict__ bias,
    __nv_bfloat16* __restrict__ oh, __nv_bfloat16* __restrict__ ol)
{
    int i4 = blockIdx.x * 256 + threadIdx.x;      // float4 index over B*FF/4
    int i  = i4 * 4;
    int c  = i & (FFc - 1);
    const size_t STR = (size_t)Bc * FFc;
    float4 a = *(const float4*)&p[i];
    float4 b = *(const float4*)&p[STR + i];
    float xs[4] = {a.x + b.x, a.y + b.y, a.z + b.z, a.w + b.w};
    __align__(8) __nv_bfloat16 th[4], tl[4];
#pragma unroll
    for (int e = 0; e < 4; e++) {
        float v = fmaxf(xs[e] + bias[c + e], 0.0f);
        __nv_bfloat16 vh = __float2bfloat16(v);
        th[e] = vh;
        tl[e] = __float2bfloat16(v - __bfloat162float(vh));
    }
    *(uint2*)&oh[i] = *(uint2*)th;
    *(uint2*)&ol[i] = *(uint2*)tl;
}

// ---------------- fused linear-attention state update ------------------------
// One block per (b,h). Fuses: QKV split-K(4) reduce + bias + elu(+1);
// S_out = S + k v^T, num = q . S_out, den = q.(Z+k)+eps, attn = num/den (hi/lo).
// Batched float4 loads on the S stream (MLP=4), then fma+store.
#define RSTR 68

__global__ __launch_bounds__(256) void attn_state_kernel(
    const float* __restrict__ S_in, const float* __restrict__ Z_in,
    const float* __restrict__ qkvp,
    const float* __restrict__ bq, const float* __restrict__ bk,
    const float* __restrict__ bv,
    float* __restrict__ S_out, float* __restrict__ Z_out,
    __nv_bfloat16* __restrict__ ah, __nv_bfloat16* __restrict__ al)
{
    int bh = blockIdx.x;                 // 0 .. B*H-1
    int t  = threadIdx.x;                // 256 threads
    __shared__ float qs[Dc], ks[Dc], vs[Dc];
    __shared__ float rnum[16 * RSTR];
    __shared__ float red64[Dc];
    __shared__ float s_den;

    int voff = bh * Dc;                  // == b*HID + h*D
    if (t < Dc) {
        int c = ((bh & (Hc - 1)) << 6) + t;          // column within HID
        float qq = bq[c], kk = bk[c], vv = bv[c];
#pragma unroll
        for (int p = 0; p < 4; p++) {
            qq += qkvp[(size_t)p * MNc + voff + t];
            kk += qkvp[(size_t)(4 + p) * MNc + voff + t];
            vv += qkvp[(size_t)(8 + p) * MNc + voff + t];
        }
        qq = (qq > 0.0f) ? (qq + 1.0f) : expf(qq);   // elu(x)+1
        kk = (kk > 0.0f) ? (kk + 1.0f) : expf(kk);
        qs[t] = qq; ks[t] = kk; vs[t] = vv;
        float zn = Z_in[voff + t] + kk;
        Z_out[voff + t] = zn;
        red64[t] = qq * zn;
    }
    __syncthreads();
    if (t < 32) {
        float s = red64[t] + red64[t + 32];
#pragma unroll
        for (int o = 16; o > 0; o >>= 1) s += __shfl_down_sync(0xffffffffu, s, o);
        if (t == 0) s_den = s + EPS_ATTN;
    }

    const int m4 = (t & 15) * 4;         // 4 consecutive columns
    const int dg = t >> 4;               // row group 0..15
    size_t base = (size_t)bh * (Dc * Dc) + (size_t)dg * Dc + m4;

    // batched loads (4 independent LDG.128 in flight)
    float4 s4[4];
#pragma unroll
    for (int i = 0; i < 4; i++) s4[i] = *(const float4*)&S_in[base + (size_t)i * 16 * Dc];

    float vm0 = vs[m4 + 0], vm1 = vs[m4 + 1], vm2 = vs[m4 + 2], vm3 = vs[m4 + 3];
    float pn[4] = {0.0f, 0.0f, 0.0f, 0.0f};
#pragma unroll
    for (int i = 0; i < 4; i++) {
        int d = dg + i * 16;
        float kd = ks[d], qd = qs[d];
        float4 sn;
        sn.x = fmaf(kd, vm0, s4[i].x);
        sn.y = fmaf(kd, vm1, s4[i].y);
        sn.z = fmaf(kd, vm2, s4[i].z);
        sn.w = fmaf(kd, vm3, s4[i].w);
        *(float4*)&S_out[base + (size_t)i * 16 * Dc] = sn;
        pn[0] = fmaf(qd, sn.x, pn[0]);
        pn[1] = fmaf(qd, sn.y, pn[1]);
        pn[2] = fmaf(qd, sn.z, pn[2]);
        pn[3] = fmaf(qd, sn.w, pn[3]);
    }
    *(float4*)&rnum[dg * RSTR + m4] = *(float4*)pn;
    __syncthreads();

    if (t < Dc) {
        float num = 0.0f;
#pragma unroll
        for (int g = 0; g < 16; g++) num += rnum[g * RSTR + t];
        float av = num / s_den;
        __nv_bfloat16 vh = __float2bfloat16(av);
        ah[voff + t] = vh;
        al[voff + t] = __float2bfloat16(av - __bfloat162float(vh));
    }
}

// ---------------- LayerNorm (fuses split-K reduce + bias + residual) ---------
__global__ __launch_bounds__(256) void ln_kernel(
    const float* __restrict__ parts, int nparts, int partStride,
    const float* __restrict__ bias, const float* __restrict__ res,
    const float* __restrict__ g, const float* __restrict__ b,
    float* __restrict__ out,
    __nv_bfloat16* __restrict__ oh, __nv_bfloat16* __restrict__ ol)
{
    int row = blockIdx.x;                // 0..B-1
    int t   = threadIdx.x;               // 256 threads, 2 elems each
    float vv[2];
#pragma unroll
    for (int r = 0; r < 2; r++) {
        int c = t + 256 * r;
        size_t idx = (size_t)row * HIDc + c;
        float x = 0.0f;
        for (int p = 0; p < nparts; p++) x += parts[(size_t)p * partStride + idx];
        if (bias) x += bias[c];
        if (res)  x += res[idx];
        vv[r] = x;
    }
    float s = vv[0] + vv[1];
    float qsum = vv[0] * vv[0] + vv[1] * vv[1];
#pragma unroll
    for (int o = 16; o > 0; o >>= 1) {
        s    += __shfl_down_sync(0xffffffffu, s, o);
        qsum += __shfl_down_sync(0xffffffffu, qsum, o);
    }
    __shared__ float ss[8], sq[8];
    __shared__ float s_mean, s_rstd;
    int warp = t >> 5, lane = t & 31;
    if (lane == 0) { ss[warp] = s; sq[warp] = qsum; }
    __syncthreads();
    if (t == 0) {
        float S = 0.0f, Q = 0.0f;
#pragma unroll
        for (int w = 0; w < 8; w++) { S += ss[w]; Q += sq[w]; }
        float mean = S * (1.0f / (float)HIDc);
        float var  = Q * (1.0f / (float)HIDc) - mean * mean;
        s_mean = mean;
        s_rstd = rsqrtf(var + EPS_LN);
    }
    __syncthreads();
#pragma unroll
    for (int r = 0; r < 2; r++) {
        int c = t + 256 * r;
        size_t idx = (size_t)row * HIDc + c;
        float y = (vv[r] - s_mean) * s_rstd * g[c] + b[c];
        out[idx] = y;
        if (oh) {
            __nv_bfloat16 vh = __float2bfloat16(y);
            oh[idx] = vh;
            ol[idx] = __float2bfloat16(y - __bfloat162float(vh));
        }
    }
}

// ---------------- launcher ----------------------------------------------------
extern "C" void kernel_launch(void* const* d_in, const int* in_sizes, int n_in,
                              void* d_out, int out_size)
{
    (void)in_sizes; (void)n_in; (void)out_size;

    const int*   x     = (const int*)  d_in[0];
    const int*   pos   = (const int*)  d_in[1];
    const float* S     = (const float*)d_in[2];
    const float* Z     = (const float*)d_in[3];
    const float* emb   = (const float*)d_in[4];
    const float* Wq    = (const float*)d_in[5];
    const float* bq    = (const float*)d_in[6];
    const float* Wk    = (const float*)d_in[7];
    const float* bk    = (const float*)d_in[8];
    const float* Wv    = (const float*)d_in[9];
    const float* bv    = (const float*)d_in[10];
    const float* Wo    = (const float*)d_in[11];
    const float* bo    = (const float*)d_in[12];
    const float* W1    = (const float*)d_in[13];
    const float* b1    = (const float*)d_in[14];
    const float* W2    = (const float*)d_in[15];
    const float* b2    = (const float*)d_in[16];
    const float* ln1_g = (const float*)d_in[17];
    const float* ln1_b = (const float*)d_in[18];
    const float* ln2_g = (const float*)d_in[19];
    const float* ln2_b = (const float*)d_in[20];
    const float* lnf_g = (const float*)d_in[21];
    const float* lnf_b = (const float*)d_in[22];

    float* h_buf;          cudaGetSymbolAddress((void**)&h_buf,  g_h);
    __nv_bfloat16* hh;     cudaGetSymbolAddress((void**)&hh,     g_hh);
    __nv_bfloat16* hl;     cudaGetSymbolAddress((void**)&hl,     g_hl);
    __nv_bfloat16* ahp;    cudaGetSymbolAddress((void**)&ahp,    g_ah);
    __nv_bfloat16* alp;    cudaGetSymbolAddress((void**)&alp,    g_al);
    __nv_bfloat16* fh;     cudaGetSymbolAddress((void**)&fh,     g_fh);
    __nv_bfloat16* fl;     cudaGetSymbolAddress((void**)&fl,     g_fl);
    float* p_buf;          cudaGetSymbolAddress((void**)&p_buf,  g_part);
    float* qkvp;           cudaGetSymbolAddress((void**)&qkvp,   g_qkvp);
    __nv_bfloat16* whi;    cudaGetSymbolAddress((void**)&whi,    g_whi);
    __nv_bfloat16* wlo;    cudaGetSymbolAddress((void**)&wlo,    g_wlo);

    const size_t SZ = (size_t)Bc * Hc * Dc * Dc;  // 8388608 per layer
    const size_t ZZ = (size_t)Bc * Hc * Dc;       // 131072  per layer
    const size_t MN = (size_t)MNc;                // 131072

    float* out   = (float*)d_out;
    float* out_h = out;                           // [B,HID]
    float* out_S = out + MN;                      // [L,B,H,D,D]
    float* out_Z = out + MN + (size_t)Lc * SZ;    // [L,B,H,D]

    // weights -> bf16 hi/lo (once per call)
    split_weights_kernel<<<WTOT / 8 / 256, 256>>>(Wq, Wk, Wv, Wo, W1, W2, whi, wlo);

    // embedding + positional encoding (fp32 + hi/lo)
    embed_kernel<<<(Bc * HIDc) / 256, 256>>>(x, pos, emb, h_buf, hh, hl);

    for (int l = 0; l < Lc; l++) {
        const __nv_bfloat16* WLh = whi + (size_t)l * WPL;
        const __nv_bfloat16* WLl = wlo + (size_t)l * WPL;

        // QKV: split-K=4 per matrix -> 384 blocks, raw fp32 partials
        gemm_qkv_bf16_kernel<<<dim3(HIDc / 64, Bc / 64, 12), 256>>>(
            hh, hl, WLh, WLl, qkvp);

        // fused QKV-reduce + bias + elu(+1) + S/Z update + attention (hi/lo out)
        attn_state_kernel<<<Bc * Hc, 256>>>(
            S + (size_t)l * SZ, Z + (size_t)l * ZZ,
            qkvp, bq + l * HIDc, bk + l * HIDc, bv + l * HIDc,
            out_S + (size_t)l * SZ, out_Z + (size_t)l * ZZ, ahp, alp);

        // O projection, split-K=8 (256 blocks)
        gemm_bf16_kernel<<<dim3(HIDc / 64, Bc / 64, 8), 256>>>(
            ahp, alp, WLh + OFF_WO, WLl + OFF_WO, nullptr, p_buf,
            Bc, HIDc, HIDc, 0);

        // h = LN1(h + attn@Wo + bo)  (+ hi/lo for FF1)
        ln_kernel<<<Bc, 256>>>(p_buf, 8, (int)MN, bo + l * HIDc, h_buf,
                               ln1_g + l * HIDc, ln1_b + l * HIDc, h_buf, hh, hl);

        // FF1, split-K=2 (256 blocks); bias+relu+hi/lo in reduce
        gemm_bf16_kernel<<<dim3(FFc / 64, Bc / 64, 2), 256>>>(
            hh, hl, WLh + OFF_W1, WLl + OFF_W1, nullptr, p_buf,
            Bc, FFc, HIDc, 0);
        reduce_bias_relu_kernel<<<(Bc * FFc / 4) / 256, 256>>>(
            p_buf, b1 + l * FFc, fh, fl);

        // FF2, split-K=8 (256 blocks)
        gemm_bf16_kernel<<<dim3(HIDc / 64, Bc / 64, 8), 256>>>(
            fh, fl, WLh + OFF_W2, WLl + OFF_W2, nullptr, p_buf,
            Bc, HIDc, FFc, 0);

        // h = LN2(h + ff)  (+ hi/lo for next layer's QKV)
        ln_kernel<<<Bc, 256>>>(p_buf, 8, (int)MN, b2 + l * HIDc, h_buf,
                               ln2_g + l * HIDc, ln2_b + l * HIDc, h_buf, hh, hl);
    }

    // final LayerNorm straight into d_out
    ln_kernel<<<Bc, 256>>>(h_buf, 1, 0, nullptr, nullptr, lnf_g, lnf_b, out_h,
                           nullptr, nullptr);
}